// round 7
// baseline (speedup 1.0000x reference)
#include <cuda_runtime.h>
#include <cuda_bf16.h>
#include <cstdint>

#define NB  2
#define CC  512
#define THW 6272
#define CT  (CC*THW)
#define EEL ((size_t)THW*(size_t)THW)
#define K3  (3*CC)                         // 1536

// ---------------- device scratch ----------------
__device__ float g_pmwz[NB*(size_t)1024*THW];        // rows 0:512 = pm, 512:1024 = wz (fp32)
__device__ float g_me[NB*CT];                        // mask_energy fp32 (softmax in place)
__device__ __nv_bfloat16 g_att [NB*EEL];             // energy -> attention bf16 [t,s]
__device__ __nv_bfloat16 g_x3  [NB*(size_t)THW*K3]; // [t, x_hi|x_lo|x_hi]
__device__ __nv_bfloat16 g_Wmz3[1024*K3];            // rows 0:512 Wm3, 512:1024 Wz3 [o, hi|hi|lo]
__device__ __nv_bfloat16 g_maskT[NB*CT];             // mask^T[t,c] bf16
__device__ __nv_bfloat16 g_Wb  [2][CC*CC];           // Wh,Wg bf16 [o,c]
__device__ __nv_bfloat16 g_phxpg[NB*(size_t)THW*1024]; // [t, phx|pg] bf16
__device__ __nv_bfloat16 g_phm [NB*CT];              // [c,s] bf16
__device__ float g_bhg[1024];
__device__ float g_bmz[1024];
__device__ float g_scale[CC];
__device__ float g_shift[CC];

// ---------------- helpers ----------------
__device__ __forceinline__ uint32_t smem_u32(const void* p) {
    uint32_t a;
    asm("{ .reg .u64 t; cvta.to.shared.u64 t, %1; cvt.u32.u64 %0, t; }" : "=r"(a) : "l"(p));
    return a;
}
#define SWZ128(o) ((o) ^ (((o) >> 3) & 0x70))
__device__ __forceinline__ void cp16(uint32_t s, const void* g) {
    asm volatile("cp.async.cg.shared.global [%0], [%1], 16;" :: "r"(s), "l"(g));
}
#define CP_COMMIT() asm volatile("cp.async.commit_group;" ::: "memory")
#define CP_WAIT(n)  asm volatile("cp.async.wait_group %0;" :: "n"(n) : "memory")

__device__ __forceinline__ void ldmx4(uint32_t& r0, uint32_t& r1, uint32_t& r2, uint32_t& r3,
                                      uint32_t addr) {
    asm volatile("ldmatrix.sync.aligned.m8n8.x4.shared.b16 {%0,%1,%2,%3}, [%4];"
                 : "=r"(r0), "=r"(r1), "=r"(r2), "=r"(r3) : "r"(addr));
}
__device__ __forceinline__ void mma_bf16(float* d, const uint32_t* a, const uint32_t* b) {
    asm volatile("mma.sync.aligned.m16n8k16.row.col.f32.bf16.bf16.f32 "
                 "{%0,%1,%2,%3}, {%4,%5,%6,%7}, {%8,%9}, {%0,%1,%2,%3};"
                 : "+f"(d[0]), "+f"(d[1]), "+f"(d[2]), "+f"(d[3])
                 : "r"(a[0]), "r"(a[1]), "r"(a[2]), "r"(a[3]), "r"(b[0]), "r"(b[1]));
}

// ================= bf16 HMMA TN GEMM, paired m-tiles =================
// C[m,n] = sum_k A[m,k]*B[n,k] (+bias_m[m]) (+bias_n[n])
// CTA computes a 256x128 output: m-tiles {mA, mB} share one B tile.
// grid.y = ceil((M/128)/2); last CTA may duplicate its m-tile (benign).
// 512 threads, 16 warps 4(m)x4(n), warp tile 64x32, 3-stage cp.async, 144KB smem.
#define STAGES 3
#define STAGE_BYTES 49152   // A 32KB + B 16KB
__global__ void __launch_bounds__(512, 1)
gemm_bf16_mma(const __nv_bfloat16* __restrict__ A, const __nv_bfloat16* __restrict__ B,
              void* __restrict__ Cv, int out_bf16,
              const float* __restrict__ bias_m, const float* __restrict__ bias_n,
              int M, int N, int K, int ldA, int ldB,
              long long sA, long long sB, long long sC)
{
    extern __shared__ char smem[];
    const uint32_t sb = smem_u32(smem);
    const int tid = threadIdx.x, wid = tid >> 5, lane = tid & 31;
    const int wm = wid & 3, wn = wid >> 2;          // 4 (m) x 4 (n)
    const int m_w = wm * 64, n_w = wn * 32;         // within 256 x 128 tile

    uint32_t bufA[STAGES], bufB[STAGES];
#pragma unroll
    for (int s = 0; s < STAGES; s++) { bufA[s] = sb + s * STAGE_BYTES; bufB[s] = bufA[s] + 32768; }

    int mA = blockIdx.y * 256;
    int mB = mA + 128;
    if (mB >= M) mB = mA;                            // duplicate tile (identical writes)
    const int n0 = blockIdx.x * 128;

    const char* Az = (const char*)(A + (long long)blockIdx.z * sA);
    const char* Bz = (const char*)(B + (long long)blockIdx.z * sB);
    const long long rbA = (long long)ldA * 2;
    const long long rbB = (long long)ldB * 2;
    const int nc = K >> 6;

    // precompute per-thread global row pointers for loads
    const char* gA[4];
    const char* gB[2];
#pragma unroll
    for (int i = 0; i < 4; i++) {
        int seg = tid + i * 512;            // 0..2047
        int row = seg >> 3;                 // 0..255
        int col = (seg & 7) << 4;
        int grow = (row < 128) ? (mA + row) : (mB + row - 128);
        gA[i] = Az + (long long)grow * rbA + col;
    }
#pragma unroll
    for (int i = 0; i < 2; i++) {
        int seg = tid + i * 512;            // 0..1023
        int row = seg >> 3;                 // 0..127
        int col = (seg & 7) << 4;
        gB[i] = Bz + (long long)(n0 + row) * rbB + col;
    }
    uint32_t offA[4], offB[2];
#pragma unroll
    for (int i = 0; i < 4; i++) {
        int seg = tid + i * 512;
        offA[i] = SWZ128((uint32_t)((seg >> 3) * 128 + ((seg & 7) << 4)));
    }
#pragma unroll
    for (int i = 0; i < 2; i++) {
        int seg = tid + i * 512;
        offB[i] = SWZ128((uint32_t)((seg >> 3) * 128 + ((seg & 7) << 4)));
    }

    auto load_chunk = [&](int c, int s) {
        long long cb = (long long)c * 128;
#pragma unroll
        for (int i = 0; i < 4; i++) cp16(bufA[s] + offA[i], gA[i] + cb);
#pragma unroll
        for (int i = 0; i < 2; i++) cp16(bufB[s] + offB[i], gB[i] + cb);
    };

    float acc[4][4][4];
#pragma unroll
    for (int i = 0; i < 4; i++)
#pragma unroll
        for (int j = 0; j < 4; j++)
#pragma unroll
            for (int q = 0; q < 4; q++) acc[i][j][q] = 0.f;

    const int grp = lane >> 3, rw = lane & 7;
    const int a_row = (grp & 1) * 8 + rw;
    const int a_kh  = (grp >> 1) * 16;
    const int b_row = (grp >> 1) * 8 + rw;
    const int b_kh  = (grp & 1) * 16;

    load_chunk(0, 0); CP_COMMIT();
    if (nc > 1) { load_chunk(1, 1); CP_COMMIT(); }

    for (int c = 0; c < nc; c++) {
        if (c + 1 < nc) { CP_WAIT(1); } else { CP_WAIT(0); }
        __syncthreads();
        const uint32_t sa = bufA[c % STAGES], sbm = bufB[c % STAGES];
#pragma unroll
        for (int kk = 0; kk < 4; kk++) {
            const int kb = kk * 32;
            uint32_t a[4][4], b[4][2];
#pragma unroll
            for (int mt = 0; mt < 4; mt++) {
                int row = m_w + mt * 16 + a_row;
                uint32_t ad = sa + SWZ128((uint32_t)(row * 128 + kb + a_kh));
                ldmx4(a[mt][0], a[mt][1], a[mt][2], a[mt][3], ad);
            }
#pragma unroll
            for (int np = 0; np < 2; np++) {
                int row = n_w + np * 16 + b_row;
                uint32_t bd = sbm + SWZ128((uint32_t)(row * 128 + kb + b_kh));
                uint32_t r0, r1, r2, r3;
                ldmx4(r0, r1, r2, r3, bd);
                b[np * 2][0] = r0; b[np * 2][1] = r1;
                b[np * 2 + 1][0] = r2; b[np * 2 + 1][1] = r3;
            }
#pragma unroll
            for (int mt = 0; mt < 4; mt++)
#pragma unroll
                for (int nt = 0; nt < 4; nt++)
                    mma_bf16(acc[mt][nt], a[mt], b[nt]);
        }
        __syncthreads();
        if (c + 2 < nc) { load_chunk(c + 2, (c + 2) % STAGES); CP_COMMIT(); }
    }

    // epilogue
    const int r_lo = lane >> 2, c_off = (lane & 3) * 2;
    const int m_base = (wm < 2) ? (mA + wm * 64) : (mB + (wm - 2) * 64);
#pragma unroll
    for (int mt = 0; mt < 4; mt++) {
        int row = m_base + mt * 16 + r_lo;
#pragma unroll
        for (int half = 0; half < 2; half++) {
            int r = row + half * 8;
            float bmv = bias_m ? bias_m[r] : 0.f;
            long long base = (long long)blockIdx.z * sC + (long long)r * N + n0 + n_w + c_off;
#pragma unroll
            for (int nt = 0; nt < 4; nt++) {
                float v0 = acc[mt][nt][half * 2 + 0] + bmv;
                float v1 = acc[mt][nt][half * 2 + 1] + bmv;
                int col = n0 + n_w + nt * 8 + c_off;
                if (bias_n) { v0 += bias_n[col]; v1 += bias_n[col + 1]; }
                if (out_bf16) {
                    __nv_bfloat162 h2 = __floats2bfloat162_rn(v0, v1);
                    *reinterpret_cast<__nv_bfloat162*>((__nv_bfloat16*)Cv + base + nt * 8) = h2;
                } else {
                    *reinterpret_cast<float2*>((float*)Cv + base + nt * 8) = make_float2(v0, v1);
                }
            }
        }
    }
}

// ---------------- transpose + hi/lo split: x [c,t] fp32 -> x3 [t, hi|lo|hi] ----------------
__global__ void split_x(const float* __restrict__ in, __nv_bfloat16* __restrict__ out,
                        long long sIn, long long sOut)
{
    __shared__ float tile[32][33];
    const float* ib = in + (long long)blockIdx.z * sIn;
    __nv_bfloat16* ob = out + (long long)blockIdx.z * sOut;
    int t0 = blockIdx.x * 32, c0 = blockIdx.y * 32;
    int x = threadIdx.x, y = threadIdx.y;
#pragma unroll
    for (int i = 0; i < 32; i += 8)
        tile[y + i][x] = ib[(long long)(c0 + y + i) * THW + t0 + x];
    __syncthreads();
#pragma unroll
    for (int i = 0; i < 32; i += 8) {
        float v = tile[x][y + i];
        __nv_bfloat16 hi = __float2bfloat16(v);
        __nv_bfloat16 lo = __float2bfloat16(v - __bfloat162float(hi));
        long long row = (long long)(t0 + y + i) * K3;
        ob[row + c0 + x]            = hi;
        ob[row + CC + c0 + x]       = lo;
        ob[row + 2 * CC + c0 + x]   = hi;
    }
}

// ---------------- Wm,Wz [o,c] fp32 -> Wmz3 [o, hi|hi|lo] ----------------
__global__ void split_wmz(const float* __restrict__ Wm, const float* __restrict__ Wz,
                          __nv_bfloat16* __restrict__ out)
{
    int i = blockIdx.x * blockDim.x + threadIdx.x;
    if (i >= 2 * CC * CC) return;
    int o = i / CC, c = i - o * CC;
    float v = (o < CC) ? Wm[o * CC + c] : Wz[(o - CC) * CC + c];
    __nv_bfloat16 hi = __float2bfloat16(v);
    __nv_bfloat16 lo = __float2bfloat16(v - __bfloat162float(hi));
    out[(long long)o * K3 + c]          = hi;
    out[(long long)o * K3 + CC + c]     = hi;
    out[(long long)o * K3 + 2 * CC + c] = lo;
}

// ---------------- transpose + fp32->bf16 (mask^T) ----------------
__global__ void transpose_cvt(const float* __restrict__ in, __nv_bfloat16* __restrict__ out,
                              int R, int Ccols, long long sIn, long long sOut)
{
    __shared__ float tile[32][33];
    const float* ib = in + (long long)blockIdx.z * sIn;
    __nv_bfloat16* ob = out + (long long)blockIdx.z * sOut;
    int c0 = blockIdx.x * 32, r0 = blockIdx.y * 32;
    int x = threadIdx.x, y = threadIdx.y;
#pragma unroll
    for (int i = 0; i < 32; i += 8)
        tile[y + i][x] = ib[(long long)(r0 + y + i) * Ccols + c0 + x];
    __syncthreads();
#pragma unroll
    for (int i = 0; i < 32; i += 8)
        ob[(long long)(c0 + y + i) * R + r0 + x] = __float2bfloat16(tile[x][y + i]);
}

// ---------------- misc small prep ----------------
__global__ void cvt_bf16(const float* __restrict__ in, __nv_bfloat16* __restrict__ out, int n)
{
    int i = blockIdx.x * blockDim.x + threadIdx.x;
    if (i < n) out[i] = __float2bfloat16(in[i]);
}
__global__ void concat2(const float* __restrict__ a, const float* __restrict__ b,
                        float* __restrict__ out)
{
    int i = blockIdx.x * blockDim.x + threadIdx.x;
    if (i < CC) out[i] = a[i];
    else if (i < 2 * CC) out[i] = b[i - CC];
}

// ---------------- softmax bf16 in-place ----------------
__global__ void __launch_bounds__(256)
softmax_b16(__nv_bfloat16* __restrict__ data, int rowlen)
{
    __nv_bfloat16* p = data + (long long)blockIdx.x * rowlen;
    const int tid = threadIdx.x;
    __shared__ float red[8];

    float v[25];
    float mx = -3.0e38f;
#pragma unroll
    for (int i = 0; i < 25; i++) {
        int idx = tid + (i << 8);
        v[i] = (idx < rowlen) ? __bfloat162float(p[idx]) : -3.0e38f;
        mx = fmaxf(mx, v[i]);
    }
#pragma unroll
    for (int o = 16; o; o >>= 1) mx = fmaxf(mx, __shfl_xor_sync(0xffffffffu, mx, o));
    if ((tid & 31) == 0) red[tid >> 5] = mx;
    __syncthreads();
    mx = red[0];
#pragma unroll
    for (int w = 1; w < 8; w++) mx = fmaxf(mx, red[w]);
    __syncthreads();

    float s = 0.f;
#pragma unroll
    for (int i = 0; i < 25; i++) { v[i] = __expf(v[i] - mx); s += v[i]; }
#pragma unroll
    for (int o = 16; o; o >>= 1) s += __shfl_xor_sync(0xffffffffu, s, o);
    if ((tid & 31) == 0) red[tid >> 5] = s;
    __syncthreads();
    s = 0.f;
#pragma unroll
    for (int w = 0; w < 8; w++) s += red[w];
    float inv = 1.f / s;
#pragma unroll
    for (int i = 0; i < 25; i++) {
        int idx = tid + (i << 8);
        if (idx < rowlen) p[idx] = __float2bfloat16(v[i] * inv);
    }
}

// ---------------- softmax fp32 in-place ----------------
__global__ void __launch_bounds__(256)
softmax_rows(float* __restrict__ data, int rowlen)
{
    float* p = data + (long long)blockIdx.x * rowlen;
    const int tid = threadIdx.x;
    __shared__ float red[8];

    float v[25];
    float mx = -3.0e38f;
#pragma unroll
    for (int i = 0; i < 25; i++) {
        int idx = tid + (i << 8);
        v[i] = (idx < rowlen) ? p[idx] : -3.0e38f;
        mx = fmaxf(mx, v[i]);
    }
#pragma unroll
    for (int o = 16; o; o >>= 1) mx = fmaxf(mx, __shfl_xor_sync(0xffffffffu, mx, o));
    if ((tid & 31) == 0) red[tid >> 5] = mx;
    __syncthreads();
    mx = red[0];
#pragma unroll
    for (int w = 1; w < 8; w++) mx = fmaxf(mx, red[w]);
    __syncthreads();

    float s = 0.f;
#pragma unroll
    for (int i = 0; i < 25; i++) { v[i] = __expf(v[i] - mx); s += v[i]; }
#pragma unroll
    for (int o = 16; o; o >>= 1) s += __shfl_xor_sync(0xffffffffu, s, o);
    if ((tid & 31) == 0) red[tid >> 5] = s;
    __syncthreads();
    s = 0.f;
#pragma unroll
    for (int w = 0; w < 8; w++) s += red[w];
    float inv = 1.f / s;
#pragma unroll
    for (int i = 0; i < 25; i++) {
        int idx = tid + (i << 8);
        if (idx < rowlen) p[idx] = v[i] * inv;
    }
}

// ---------------- BN stats ----------------
__global__ void __launch_bounds__(256)
bn_stats(const float* __restrict__ pmwz, const float* __restrict__ bn_w,
         const float* __restrict__ bn_b, float* __restrict__ scale,
         float* __restrict__ shift)
{
    int c = blockIdx.x;
    int tid = threadIdx.x;
    const long long rowOff = (long long)(512 + c) * THW;
    float s = 0.f, sq = 0.f;
    for (int i = tid; i < NB * THW; i += 256) {
        int n = i / THW, t = i - n * THW;
        float v = pmwz[(long long)n * 1024 * THW + rowOff + t];
        s += v;
        sq = fmaf(v, v, sq);
    }
    __shared__ float r1[8], r2[8];
#pragma unroll
    for (int o = 16; o; o >>= 1) {
        s  += __shfl_xor_sync(0xffffffffu, s,  o);
        sq += __shfl_xor_sync(0xffffffffu, sq, o);
    }
    if ((tid & 31) == 0) { r1[tid >> 5] = s; r2[tid >> 5] = sq; }
    __syncthreads();
    if (tid == 0) {
        s = 0.f; sq = 0.f;
#pragma unroll
        for (int w = 0; w < 8; w++) { s += r1[w]; sq += r2[w]; }
        const float invn = 1.f / (float)(NB * THW);
        float mu  = s * invn;
        float var = sq * invn - mu * mu;
        float sc  = bn_w[c] * rsqrtf(var + 1e-5f);
        scale[c] = sc;
        shift[c] = bn_b[c] - mu * sc;
    }
}

// ---------------- final combine ----------------
__global__ void final_k(const float* __restrict__ pmwz, const float* __restrict__ ma,
                        const float* __restrict__ scale, const float* __restrict__ shift,
                        const float* __restrict__ gamma, float* __restrict__ out)
{
    long long i = (long long)blockIdx.x * blockDim.x + threadIdx.x;
    if (i >= (long long)NB * CT) return;
    int n = (int)(i / CT);
    int c = (int)((i / THW) % CC);
    int t = (int)(i % THW);
    long long base = (long long)n * 1024 * THW + (long long)c * THW + t;
    float pmv = pmwz[base];
    float wzv = pmwz[base + (long long)512 * THW];
    out[i] = gamma[0] * pmv * ma[i] + fmaf(wzv, scale[c], shift[c]);
}

// ---------------- launch ----------------
extern "C" void kernel_launch(void* const* d_in, const int* in_sizes, int n_in,
                              void* d_out, int out_size)
{
    const float* x    = (const float*)d_in[0];
    const float* mask = (const float*)d_in[1];
    const float* Wh   = (const float*)d_in[2];
    const float* bh   = (const float*)d_in[3];
    const float* Wg   = (const float*)d_in[4];
    const float* bg   = (const float*)d_in[5];
    const float* Wm   = (const float*)d_in[6];
    const float* bm   = (const float*)d_in[7];
    const float* Wz   = (const float*)d_in[8];
    const float* bz   = (const float*)d_in[9];
    const float* bn_w = (const float*)d_in[10];
    const float* bn_b = (const float*)d_in[11];
    const float* gamma= (const float*)d_in[12];
    float* out = (float*)d_out;

    float *pmwz, *me, *bhg, *bmz, *scale, *shift;
    __nv_bfloat16 *att, *x3, *Wmz3, *maskT, *Wb, *phxpg, *phm;
    cudaGetSymbolAddress((void**)&pmwz,  g_pmwz);
    cudaGetSymbolAddress((void**)&me,    g_me);
    cudaGetSymbolAddress((void**)&att,   g_att);
    cudaGetSymbolAddress((void**)&x3,    g_x3);
    cudaGetSymbolAddress((void**)&Wmz3,  g_Wmz3);
    cudaGetSymbolAddress((void**)&maskT, g_maskT);
    cudaGetSymbolAddress((void**)&Wb,    g_Wb);
    cudaGetSymbolAddress((void**)&phxpg, g_phxpg);
    cudaGetSymbolAddress((void**)&phm,   g_phm);
    cudaGetSymbolAddress((void**)&bhg,   g_bhg);
    cudaGetSymbolAddress((void**)&bmz,   g_bmz);
    cudaGetSymbolAddress((void**)&scale, g_scale);
    cudaGetSymbolAddress((void**)&shift, g_shift);

    const long long EE = (long long)EEL;
    const long long sX3 = (long long)THW * K3;
    const long long sHG = (long long)THW * 1024;
    const long long sMZ = (long long)1024 * THW;
    const int SMEM_GEMM = STAGES * STAGE_BYTES;   // 144KB
    cudaFuncSetAttribute(gemm_bf16_mma, cudaFuncAttributeMaxDynamicSharedMemorySize, SMEM_GEMM);

    const dim3 t32(32, 8);
    auto pairs = [](int M) { return ((M / 128) + 1) / 2; };

    // prep
    cvt_bf16<<<(CC * CC + 255) / 256, 256>>>(Wh, Wb + 0 * CC * CC, CC * CC);
    cvt_bf16<<<(CC * CC + 255) / 256, 256>>>(Wg, Wb + 1 * CC * CC, CC * CC);
    split_wmz<<<(2 * CC * CC + 255) / 256, 256>>>(Wm, Wz, Wmz3);
    concat2<<<4, 256>>>(bh, bg, bhg);
    concat2<<<4, 256>>>(bm, bz, bmz);
    split_x<<<dim3(THW / 32, CC / 32, NB), t32>>>(x, x3, CT, sX3);
    transpose_cvt<<<dim3(THW / 32, CC / 32, NB), t32>>>(mask, maskT, CC, THW, CT, CT);

    // proj1: phxpg[t, o] = sum_c x3[t,c]*(Wh|Wg)[o,c] + bhg[o]   (bf16 out, N=1024)
    gemm_bf16_mma<<<dim3(1024 / 128, pairs(THW), NB), 512, SMEM_GEMM>>>(
        x3, Wb, phxpg, 1, nullptr, bhg, THW, 1024, CC, K3, CC, sX3, 0, sHG);

    // proj2: pmwz[o, t] = sum_k Wmz3[o,k]*x3[t,k] + bmz[o]   (fp32, M=1024, K=1536)
    gemm_bf16_mma<<<dim3(THW / 128, pairs(1024), NB), 512, SMEM_GEMM>>>(
        Wmz3, x3, pmwz, 0, bmz, nullptr, 1024, THW, K3, K3, K3, 0, sX3, sMZ);

    // phm[o, s] = sum_c Wh[o,c]*maskT[s,c] + bh[o]   (bf16)
    gemm_bf16_mma<<<dim3(THW / 128, pairs(CC), NB), 512, SMEM_GEMM>>>(
        Wb, maskT, phm, 1, bh, nullptr, CC, THW, CC, CC, CC, 0, CT, CT);

    // energy[t,s] = sum_c phx[t,c]*pg[s,c]  (bf16 out into att)
    gemm_bf16_mma<<<dim3(THW / 128, pairs(THW), NB), 512, SMEM_GEMM>>>(
        phxpg, phxpg + 512, att, 1, nullptr, nullptr, THW, THW, CC, 1024, 1024, sHG, sHG, EE);

    // attention = softmax_s(energy), bf16 in place
    softmax_b16<<<NB * THW, 256>>>(att, THW);

    // mask_energy[c,t] = sum_s phm[c,s]*att[t,s]   (fp32 out)
    gemm_bf16_mma<<<dim3(THW / 128, pairs(CC), NB), 512, SMEM_GEMM>>>(
        phm, att, me, 0, nullptr, nullptr, CC, THW, THW, THW, THW, CT, EE, CT);

    // mask_atten = softmax_t(mask_energy), in place
    softmax_rows<<<NB * CC, 256>>>(me, THW);

    // BN stats on wz rows of pmwz
    bn_stats<<<CC, 256>>>(pmwz, bn_w, bn_b, scale, shift);

    // out = gamma*pm*mask_atten + BN(wz)
    final_k<<<(NB * CT + 255) / 256, 256>>>(pmwz, me, scale, shift, gamma, out);
}

// round 8
// speedup vs baseline: 1.2553x; 1.2553x over previous
#include <cuda_runtime.h>
#include <cuda_bf16.h>
#include <cstdint>

#define NB  2
#define CC  512
#define THW 6272
#define CT  (CC*THW)
#define EEL ((size_t)THW*(size_t)THW)
#define K3  (3*CC)                         // 1536

// ---------------- device scratch ----------------
__device__ float g_wz[NB*CT];                        // fp32 Wz projection [c,t]
__device__ float g_me[NB*CT];                        // mask_energy fp32
__device__ __nv_bfloat16 g_att [NB*EEL];             // energy -> attention bf16 [t,s]
__device__ __nv_bfloat16 g_x3  [NB*(size_t)THW*K3]; // [t, x_hi|x_lo|x_hi]
__device__ __nv_bfloat16 g_Wz3 [CC*K3];              // [o, hi|hi|lo]
__device__ __nv_bfloat16 g_maskT[NB*CT];             // mask^T[t,c] bf16
__device__ __nv_bfloat16 g_Wb  [3][CC*CC];           // Wh,Wg,Wm bf16 [o,c] (Wh,Wg contiguous)
__device__ __nv_bfloat16 g_phxpg[NB*(size_t)THW*1024]; // [t, phx|pg] bf16
__device__ __nv_bfloat16 g_phm [NB*CT];              // [c,s] bf16
__device__ __nv_bfloat16 g_pm  [NB*CT];              // [c,t] bf16
__device__ float g_bhg[1024];
__device__ float g_scale[CC];
__device__ float g_shift[CC];

// ---------------- helpers ----------------
__device__ __forceinline__ uint32_t smem_u32(const void* p) {
    uint32_t a;
    asm("{ .reg .u64 t; cvta.to.shared.u64 t, %1; cvt.u32.u64 %0, t; }" : "=r"(a) : "l"(p));
    return a;
}
#define SWZ128(o) ((o) ^ (((o) >> 3) & 0x70))
__device__ __forceinline__ void cp16(uint32_t s, const void* g) {
    asm volatile("cp.async.cg.shared.global [%0], [%1], 16;" :: "r"(s), "l"(g));
}
#define CP_COMMIT() asm volatile("cp.async.commit_group;" ::: "memory")
#define CP_WAIT(n)  asm volatile("cp.async.wait_group %0;" :: "n"(n) : "memory")

__device__ __forceinline__ void ldmx4(uint32_t& r0, uint32_t& r1, uint32_t& r2, uint32_t& r3,
                                      uint32_t addr) {
    asm volatile("ldmatrix.sync.aligned.m8n8.x4.shared.b16 {%0,%1,%2,%3}, [%4];"
                 : "=r"(r0), "=r"(r1), "=r"(r2), "=r"(r3) : "r"(addr));
}
__device__ __forceinline__ void mma_bf16(float* d, const uint32_t* a, const uint32_t* b) {
    asm volatile("mma.sync.aligned.m16n8k16.row.col.f32.bf16.bf16.f32 "
                 "{%0,%1,%2,%3}, {%4,%5,%6,%7}, {%8,%9}, {%0,%1,%2,%3};"
                 : "+f"(d[0]), "+f"(d[1]), "+f"(d[2]), "+f"(d[3])
                 : "r"(a[0]), "r"(a[1]), "r"(a[2]), "r"(a[3]), "r"(b[0]), "r"(b[1]));
}

// ================= bf16 HMMA TN GEMM (R4 config, single-barrier mainloop) =================
// C[m,n] = sum_k A[m,k]*B[n,k] (+bias_m[m]) (+bias_n[n])
// A: [M,ldA] bf16 row-major, B: [N,ldB] bf16 row-major. M,N mult 128, K mult 64.
// 256 threads, 8 warps 2(m)x4(n), warp tile 64x32, CTA 128x128, 3-stage, 96KB.
#define STAGES 3
__global__ void __launch_bounds__(256)
gemm_bf16_mma(const __nv_bfloat16* __restrict__ A, const __nv_bfloat16* __restrict__ B,
              void* __restrict__ Cv, int out_bf16,
              const float* __restrict__ bias_m, const float* __restrict__ bias_n,
              int M, int N, int K, int ldA, int ldB,
              long long sA, long long sB, long long sC)
{
    extern __shared__ char smem[];
    const uint32_t sb = smem_u32(smem);
    const int tid = threadIdx.x, wid = tid >> 5, lane = tid & 31;
    const int wm = wid & 1, wn = wid >> 1;          // 2 (m) x 4 (n)
    const int m_w = wm * 64, n_w = wn * 32;

    uint32_t bufA[STAGES], bufB[STAGES];
#pragma unroll
    for (int s = 0; s < STAGES; s++) { bufA[s] = sb + s * 32768; bufB[s] = bufA[s] + 16384; }

    const int m0 = blockIdx.y * 128, n0 = blockIdx.x * 128;
    const char* Ab = (const char*)(A + (long long)blockIdx.z * sA + (long long)m0 * ldA);
    const char* Bb = (const char*)(B + (long long)blockIdx.z * sB + (long long)n0 * ldB);
    const long long rbA = (long long)ldA * 2;
    const long long rbB = (long long)ldB * 2;
    const int nc = K >> 6;

    const int lrow = tid >> 3;             // 0..31
    const int lcol = (tid & 7) << 4;       // 0..112

    auto load_chunk = [&](int c, int s) {
        const char* ga = Ab + (long long)c * 128;
        const char* gb = Bb + (long long)c * 128;
#pragma unroll
        for (int i = 0; i < 4; i++) {
            int row = lrow + i * 32;
            uint32_t off = SWZ128((uint32_t)(row * 128 + lcol));
            long long go = (long long)row;
            cp16(bufA[s] + off, ga + go * rbA + lcol);
            cp16(bufB[s] + off, gb + go * rbB + lcol);
        }
    };

    float acc[4][4][4];
#pragma unroll
    for (int i = 0; i < 4; i++)
#pragma unroll
        for (int j = 0; j < 4; j++)
#pragma unroll
            for (int q = 0; q < 4; q++) acc[i][j][q] = 0.f;

    const int grp = lane >> 3, rw = lane & 7;
    const int a_row = (grp & 1) * 8 + rw;
    const int a_kh  = (grp >> 1) * 16;
    const int b_row = (grp >> 1) * 8 + rw;
    const int b_kh  = (grp & 1) * 16;

    load_chunk(0, 0); CP_COMMIT();
    if (nc > 1) { load_chunk(1, 1); CP_COMMIT(); }

    for (int c = 0; c < nc; c++) {
        if (c + 1 < nc) { CP_WAIT(1); } else { CP_WAIT(0); }
        __syncthreads();
        // issue next-next chunk loads BEFORE compute (single barrier per iter;
        // buffer (c+2)%3 was last read in iter c-1 which precedes this barrier)
        if (c + 2 < nc) { load_chunk(c + 2, (c + 2) % STAGES); CP_COMMIT(); }
        const uint32_t sa = bufA[c % STAGES], sbm = bufB[c % STAGES];
#pragma unroll
        for (int kk = 0; kk < 4; kk++) {
            const int kb = kk * 32;
            uint32_t a[4][4], b[4][2];
#pragma unroll
            for (int mt = 0; mt < 4; mt++) {
                int row = m_w + mt * 16 + a_row;
                uint32_t ad = sa + SWZ128((uint32_t)(row * 128 + kb + a_kh));
                ldmx4(a[mt][0], a[mt][1], a[mt][2], a[mt][3], ad);
            }
#pragma unroll
            for (int np = 0; np < 2; np++) {
                int row = n_w + np * 16 + b_row;
                uint32_t bd = sbm + SWZ128((uint32_t)(row * 128 + kb + b_kh));
                uint32_t r0, r1, r2, r3;
                ldmx4(r0, r1, r2, r3, bd);
                b[np * 2][0] = r0; b[np * 2][1] = r1;
                b[np * 2 + 1][0] = r2; b[np * 2 + 1][1] = r3;
            }
#pragma unroll
            for (int mt = 0; mt < 4; mt++)
#pragma unroll
                for (int nt = 0; nt < 4; nt++)
                    mma_bf16(acc[mt][nt], a[mt], b[nt]);
        }
    }

    // epilogue
    const int r_lo = lane >> 2, c_off = (lane & 3) * 2;
#pragma unroll
    for (int mt = 0; mt < 4; mt++) {
        int row = m0 + m_w + mt * 16 + r_lo;
#pragma unroll
        for (int half = 0; half < 2; half++) {
            int r = row + half * 8;
            float bmv = bias_m ? bias_m[r] : 0.f;
            long long base = (long long)blockIdx.z * sC + (long long)r * N + n0 + n_w + c_off;
#pragma unroll
            for (int nt = 0; nt < 4; nt++) {
                float v0 = acc[mt][nt][half * 2 + 0] + bmv;
                float v1 = acc[mt][nt][half * 2 + 1] + bmv;
                int col = n0 + n_w + nt * 8 + c_off;
                if (bias_n) { v0 += bias_n[col]; v1 += bias_n[col + 1]; }
                if (out_bf16) {
                    __nv_bfloat162 h2 = __floats2bfloat162_rn(v0, v1);
                    *reinterpret_cast<__nv_bfloat162*>((__nv_bfloat16*)Cv + base + nt * 8) = h2;
                } else {
                    *reinterpret_cast<float2*>((float*)Cv + base + nt * 8) = make_float2(v0, v1);
                }
            }
        }
    }
}

// ---------------- transpose + hi/lo split: x [c,t] fp32 -> x3 [t, hi|lo|hi] ----------------
__global__ void split_x(const float* __restrict__ in, __nv_bfloat16* __restrict__ out,
                        long long sIn, long long sOut)
{
    __shared__ float tile[32][33];
    const float* ib = in + (long long)blockIdx.z * sIn;
    __nv_bfloat16* ob = out + (long long)blockIdx.z * sOut;
    int t0 = blockIdx.x * 32, c0 = blockIdx.y * 32;
    int x = threadIdx.x, y = threadIdx.y;
#pragma unroll
    for (int i = 0; i < 32; i += 8)
        tile[y + i][x] = ib[(long long)(c0 + y + i) * THW + t0 + x];
    __syncthreads();
#pragma unroll
    for (int i = 0; i < 32; i += 8) {
        float v = tile[x][y + i];
        __nv_bfloat16 hi = __float2bfloat16(v);
        __nv_bfloat16 lo = __float2bfloat16(v - __bfloat162float(hi));
        long long row = (long long)(t0 + y + i) * K3;
        ob[row + c0 + x]            = hi;
        ob[row + CC + c0 + x]       = lo;
        ob[row + 2 * CC + c0 + x]   = hi;
    }
}

// ---------------- Wz [o,c] fp32 -> Wz3 [o, hi|hi|lo] ----------------
__global__ void split_w(const float* __restrict__ in, __nv_bfloat16* __restrict__ out)
{
    int i = blockIdx.x * blockDim.x + threadIdx.x;
    if (i >= CC * CC) return;
    int o = i / CC, c = i - o * CC;
    float v = in[i];
    __nv_bfloat16 hi = __float2bfloat16(v);
    __nv_bfloat16 lo = __float2bfloat16(v - __bfloat162float(hi));
    out[(long long)o * K3 + c]          = hi;
    out[(long long)o * K3 + CC + c]     = hi;
    out[(long long)o * K3 + 2 * CC + c] = lo;
}

// ---------------- transpose + fp32->bf16 (mask^T) ----------------
__global__ void transpose_cvt(const float* __restrict__ in, __nv_bfloat16* __restrict__ out,
                              int R, int Ccols, long long sIn, long long sOut)
{
    __shared__ float tile[32][33];
    const float* ib = in + (long long)blockIdx.z * sIn;
    __nv_bfloat16* ob = out + (long long)blockIdx.z * sOut;
    int c0 = blockIdx.x * 32, r0 = blockIdx.y * 32;
    int x = threadIdx.x, y = threadIdx.y;
#pragma unroll
    for (int i = 0; i < 32; i += 8)
        tile[y + i][x] = ib[(long long)(r0 + y + i) * Ccols + c0 + x];
    __syncthreads();
#pragma unroll
    for (int i = 0; i < 32; i += 8)
        ob[(long long)(c0 + y + i) * R + r0 + x] = __float2bfloat16(tile[x][y + i]);
}

// ---------------- misc small prep ----------------
__global__ void cvt_bf16(const float* __restrict__ in, __nv_bfloat16* __restrict__ out, int n)
{
    int i = blockIdx.x * blockDim.x + threadIdx.x;
    if (i < n) out[i] = __float2bfloat16(in[i]);
}
__global__ void concat2(const float* __restrict__ a, const float* __restrict__ b,
                        float* __restrict__ out)
{
    int i = blockIdx.x * blockDim.x + threadIdx.x;
    if (i < CC) out[i] = a[i];
    else if (i < 2 * CC) out[i] = b[i - CC];
}

// ---------------- softmax bf16 in-place (attention) ----------------
__global__ void __launch_bounds__(256)
softmax_b16(__nv_bfloat16* __restrict__ data, int rowlen)
{
    __nv_bfloat16* p = data + (long long)blockIdx.x * rowlen;
    const int tid = threadIdx.x;
    __shared__ float red[8];

    float v[25];
    float mx = -3.0e38f;
#pragma unroll
    for (int i = 0; i < 25; i++) {
        int idx = tid + (i << 8);
        v[i] = (idx < rowlen) ? __bfloat162float(p[idx]) : -3.0e38f;
        mx = fmaxf(mx, v[i]);
    }
#pragma unroll
    for (int o = 16; o; o >>= 1) mx = fmaxf(mx, __shfl_xor_sync(0xffffffffu, mx, o));
    if ((tid & 31) == 0) red[tid >> 5] = mx;
    __syncthreads();
    mx = red[0];
#pragma unroll
    for (int w = 1; w < 8; w++) mx = fmaxf(mx, red[w]);
    __syncthreads();

    float s = 0.f;
#pragma unroll
    for (int i = 0; i < 25; i++) { v[i] = __expf(v[i] - mx); s += v[i]; }
#pragma unroll
    for (int o = 16; o; o >>= 1) s += __shfl_xor_sync(0xffffffffu, s, o);
    if ((tid & 31) == 0) red[tid >> 5] = s;
    __syncthreads();
    s = 0.f;
#pragma unroll
    for (int w = 0; w < 8; w++) s += red[w];
    float inv = 1.f / s;
#pragma unroll
    for (int i = 0; i < 25; i++) {
        int idx = tid + (i << 8);
        if (idx < rowlen) p[idx] = __float2bfloat16(v[i] * inv);
    }
}

// ---------------- BN stats on g_wz ----------------
__global__ void __launch_bounds__(256)
bn_stats(const float* __restrict__ wz, const float* __restrict__ bn_w,
         const float* __restrict__ bn_b, float* __restrict__ scale,
         float* __restrict__ shift)
{
    int c = blockIdx.x;
    int tid = threadIdx.x;
    float s = 0.f, sq = 0.f;
    for (int i = tid; i < NB * THW; i += 256) {
        int n = i / THW, t = i - n * THW;
        float v = wz[(long long)n * CT + (long long)c * THW + t];
        s += v;
        sq = fmaf(v, v, sq);
    }
    __shared__ float r1[8], r2[8];
#pragma unroll
    for (int o = 16; o; o >>= 1) {
        s  += __shfl_xor_sync(0xffffffffu, s,  o);
        sq += __shfl_xor_sync(0xffffffffu, sq, o);
    }
    if ((tid & 31) == 0) { r1[tid >> 5] = s; r2[tid >> 5] = sq; }
    __syncthreads();
    if (tid == 0) {
        s = 0.f; sq = 0.f;
#pragma unroll
        for (int w = 0; w < 8; w++) { s += r1[w]; sq += r2[w]; }
        const float invn = 1.f / (float)(NB * THW);
        float mu  = s * invn;
        float var = sq * invn - mu * mu;
        float sc  = bn_w[c] * rsqrtf(var + 1e-5f);
        scale[c] = sc;
        shift[c] = bn_b[c] - mu * sc;
    }
}

// ---------------- fused: mask_atten = softmax_t(me); out = gamma*pm*mask_atten + BN(wz) ----------------
// one block per (n,c) row; me/pm/wz/out all indexed at blk*THW
__global__ void __launch_bounds__(256)
softmax_final(const float* __restrict__ me, const __nv_bfloat16* __restrict__ pm,
              const float* __restrict__ wz, const float* __restrict__ scale,
              const float* __restrict__ shift, const float* __restrict__ gamma,
              float* __restrict__ out)
{
    const int blk = blockIdx.x;
    const int c = blk % CC;
    const long long base = (long long)blk * THW;
    const float* p = me + base;
    const int tid = threadIdx.x;
    __shared__ float red[8];

    float v[25];
    float mx = -3.0e38f;
#pragma unroll
    for (int i = 0; i < 25; i++) {
        int idx = tid + (i << 8);
        v[i] = (idx < THW) ? p[idx] : -3.0e38f;
        mx = fmaxf(mx, v[i]);
    }
#pragma unroll
    for (int o = 16; o; o >>= 1) mx = fmaxf(mx, __shfl_xor_sync(0xffffffffu, mx, o));
    if ((tid & 31) == 0) red[tid >> 5] = mx;
    __syncthreads();
    mx = red[0];
#pragma unroll
    for (int w = 1; w < 8; w++) mx = fmaxf(mx, red[w]);
    __syncthreads();

    float s = 0.f;
#pragma unroll
    for (int i = 0; i < 25; i++) { v[i] = __expf(v[i] - mx); s += v[i]; }
#pragma unroll
    for (int o = 16; o; o >>= 1) s += __shfl_xor_sync(0xffffffffu, s, o);
    if ((tid & 31) == 0) red[tid >> 5] = s;
    __syncthreads();
    s = 0.f;
#pragma unroll
    for (int w = 0; w < 8; w++) s += red[w];

    const float inv = 1.f / s;
    const float g  = gamma[0];
    const float sc = scale[c], sh = shift[c];
#pragma unroll
    for (int i = 0; i < 25; i++) {
        int idx = tid + (i << 8);
        if (idx < THW) {
            float ma  = v[i] * inv;
            float pmv = __bfloat162float(pm[base + idx]);
            out[base + idx] = g * pmv * ma + fmaf(wz[base + idx], sc, sh);
        }
    }
}

// ---------------- launch ----------------
extern "C" void kernel_launch(void* const* d_in, const int* in_sizes, int n_in,
                              void* d_out, int out_size)
{
    const float* x    = (const float*)d_in[0];
    const float* mask = (const float*)d_in[1];
    const float* Wh   = (const float*)d_in[2];
    const float* bh   = (const float*)d_in[3];
    const float* Wg   = (const float*)d_in[4];
    const float* bg   = (const float*)d_in[5];
    const float* Wm   = (const float*)d_in[6];
    const float* bm   = (const float*)d_in[7];
    const float* Wz   = (const float*)d_in[8];
    const float* bz   = (const float*)d_in[9];
    const float* bn_w = (const float*)d_in[10];
    const float* bn_b = (const float*)d_in[11];
    const float* gamma= (const float*)d_in[12];
    float* out = (float*)d_out;

    float *wz, *me, *bhg, *scale, *shift;
    __nv_bfloat16 *att, *x3, *Wz3, *maskT, *Wb, *phxpg, *phm, *pm;
    cudaGetSymbolAddress((void**)&wz,    g_wz);
    cudaGetSymbolAddress((void**)&me,    g_me);
    cudaGetSymbolAddress((void**)&att,   g_att);
    cudaGetSymbolAddress((void**)&x3,    g_x3);
    cudaGetSymbolAddress((void**)&Wz3,   g_Wz3);
    cudaGetSymbolAddress((void**)&maskT, g_maskT);
    cudaGetSymbolAddress((void**)&Wb,    g_Wb);
    cudaGetSymbolAddress((void**)&phxpg, g_phxpg);
    cudaGetSymbolAddress((void**)&phm,   g_phm);
    cudaGetSymbolAddress((void**)&pm,    g_pm);
    cudaGetSymbolAddress((void**)&bhg,   g_bhg);
    cudaGetSymbolAddress((void**)&scale, g_scale);
    cudaGetSymbolAddress((void**)&shift, g_shift);

    const long long EE = (long long)EEL;
    const long long sX3 = (long long)THW * K3;
    const long long sHG = (long long)THW * 1024;
    const int SMEM_GEMM = STAGES * 32768;   // 96KB
    cudaFuncSetAttribute(gemm_bf16_mma, cudaFuncAttributeMaxDynamicSharedMemorySize, SMEM_GEMM);

    const dim3 t32(32, 8);

    // prep
    cvt_bf16<<<(CC * CC + 255) / 256, 256>>>(Wh, Wb + 0 * CC * CC, CC * CC);
    cvt_bf16<<<(CC * CC + 255) / 256, 256>>>(Wg, Wb + 1 * CC * CC, CC * CC);
    cvt_bf16<<<(CC * CC + 255) / 256, 256>>>(Wm, Wb + 2 * CC * CC, CC * CC);
    split_w<<<(CC * CC + 255) / 256, 256>>>(Wz, Wz3);
    concat2<<<4, 256>>>(bh, bg, bhg);
    split_x<<<dim3(THW / 32, CC / 32, NB), t32>>>(x, x3, CT, sX3);
    transpose_cvt<<<dim3(THW / 32, CC / 32, NB), t32>>>(mask, maskT, CC, THW, CT, CT);

    // proj1 (merged phx+pg): phxpg[t,o] = sum_c x3[t,c]*(Wh|Wg)[o,c] + bhg[o]  (bf16, N=1024)
    gemm_bf16_mma<<<dim3(1024 / 128, THW / 128, NB), 256, SMEM_GEMM>>>(
        x3, Wb, phxpg, 1, nullptr, bhg, THW, 1024, CC, K3, CC, sX3, 0, sHG);

    // phm[o,s] = sum_c Wh[o,c]*maskT[s,c] + bh[o]  (bf16)
    gemm_bf16_mma<<<dim3(THW / 128, CC / 128, NB), 256, SMEM_GEMM>>>(
        Wb, maskT, phm, 1, bh, nullptr, CC, THW, CC, CC, CC, 0, CT, CT);

    // pm[o,t] = sum_c Wm[o,c]*x3[t,c] + bm[o]  (bf16, K=512 via hi part of x3)
    gemm_bf16_mma<<<dim3(THW / 128, CC / 128, NB), 256, SMEM_GEMM>>>(
        Wb + 2 * CC * CC, x3, pm, 1, bm, nullptr, CC, THW, CC, CC, K3, 0, sX3, CT);

    // wz[o,t] near-fp32 via bf16x3 split, K=1536  (fp32)
    gemm_bf16_mma<<<dim3(THW / 128, CC / 128, NB), 256, SMEM_GEMM>>>(
        Wz3, x3, wz, 0, bz, nullptr, CC, THW, K3, K3, K3, 0, sX3, CT);

    // energy[t,s] = sum_c phx[t,c]*pg[s,c]  (bf16 out into att)
    gemm_bf16_mma<<<dim3(THW / 128, THW / 128, NB), 256, SMEM_GEMM>>>(
        phxpg, phxpg + 512, att, 1, nullptr, nullptr, THW, THW, CC, 1024, 1024, sHG, sHG, EE);

    // attention = softmax_s(energy), bf16 in place
    softmax_b16<<<NB * THW, 256>>>(att, THW);

    // mask_energy[c,t] = sum_s phm[c,s]*att[t,s]  (fp32)
    gemm_bf16_mma<<<dim3(THW / 128, CC / 128, NB), 256, SMEM_GEMM>>>(
        phm, att, me, 0, nullptr, nullptr, CC, THW, THW, THW, THW, CT, EE, CT);

    // BN stats on wz (independent of me path)
    bn_stats<<<CC, 256>>>(wz, bn_w, bn_b, scale, shift);

    // fused: softmax_t(me) + final combine
    softmax_final<<<NB * CC, 256>>>(me, pm, wz, scale, shift, gamma, out);
}

// round 9
// speedup vs baseline: 1.3082x; 1.0421x over previous
#include <cuda_runtime.h>
#include <cuda_bf16.h>
#include <cuda_fp16.h>
#include <cstdint>

#define NB  2
#define CC  512
#define THW 6272
#define CT  (CC*THW)
#define EEL ((size_t)THW*(size_t)THW)
#define K3  (3*CC)                         // 1536

// ---------------- device scratch ----------------
__device__ float g_wz[NB*CT];                        // fp32 Wz projection [c,t]
__device__ float g_me[NB*CT];                        // mask_energy fp32
__device__ __half g_att [NB*EEL];                    // energy -> attention fp16 [t,s]
__device__ __nv_bfloat16 g_x3 [NB*(size_t)THW*K3];  // [t, x_hi|x_lo|x_hi] bf16 (wz branch)
__device__ __nv_bfloat16 g_Wz3[CC*K3];               // [o, hi|hi|lo] bf16
__device__ __half g_xh  [NB*CT];                     // x^T [t,c] fp16
__device__ __half g_maskT[NB*CT];                    // mask^T [s,c] fp16
__device__ __half g_whgm[3*CC*CC];                   // Wh,Wg,Wm fp16 [o,c]
__device__ __half g_phxpg[NB*(size_t)THW*1024];      // [t, phx|pg] fp16
__device__ __half g_phm [NB*CT];                     // [c,s] fp16
__device__ __half g_pm  [NB*CT];                     // [c,t] fp16
__device__ float g_bhg[1024];
__device__ float g_scale[CC];
__device__ float g_shift[CC];

// ---------------- helpers ----------------
__device__ __forceinline__ uint32_t smem_u32(const void* p) {
    uint32_t a;
    asm("{ .reg .u64 t; cvta.to.shared.u64 t, %1; cvt.u32.u64 %0, t; }" : "=r"(a) : "l"(p));
    return a;
}
#define SWZ128(o) ((o) ^ (((o) >> 3) & 0x70))
__device__ __forceinline__ void cp16(uint32_t s, const void* g) {
    asm volatile("cp.async.cg.shared.global [%0], [%1], 16;" :: "r"(s), "l"(g));
}
#define CP_COMMIT() asm volatile("cp.async.commit_group;" ::: "memory")
#define CP_WAIT(n)  asm volatile("cp.async.wait_group %0;" :: "n"(n) : "memory")

__device__ __forceinline__ void ldmx4(uint32_t& r0, uint32_t& r1, uint32_t& r2, uint32_t& r3,
                                      uint32_t addr) {
    asm volatile("ldmatrix.sync.aligned.m8n8.x4.shared.b16 {%0,%1,%2,%3}, [%4];"
                 : "=r"(r0), "=r"(r1), "=r"(r2), "=r"(r3) : "r"(addr));
}
__device__ __forceinline__ void mma_bf16(float* d, const uint32_t* a, const uint32_t* b) {
    asm volatile("mma.sync.aligned.m16n8k16.row.col.f32.bf16.bf16.f32 "
                 "{%0,%1,%2,%3}, {%4,%5,%6,%7}, {%8,%9}, {%0,%1,%2,%3};"
                 : "+f"(d[0]), "+f"(d[1]), "+f"(d[2]), "+f"(d[3])
                 : "r"(a[0]), "r"(a[1]), "r"(a[2]), "r"(a[3]), "r"(b[0]), "r"(b[1]));
}
__device__ __forceinline__ void mma_f16(uint32_t* d, const uint32_t* a, const uint32_t* b) {
    asm volatile("mma.sync.aligned.m16n8k16.row.col.f16.f16.f16.f16 "
                 "{%0,%1}, {%2,%3,%4,%5}, {%6,%7}, {%0,%1};"
                 : "+r"(d[0]), "+r"(d[1])
                 : "r"(a[0]), "r"(a[1]), "r"(a[2]), "r"(a[3]), "r"(b[0]), "r"(b[1]));
}

#define STAGES 3

// ================= fp16 HMMA TN GEMM (fp16 accumulate) =================
// C[m,n] = sum_k A[m,k]*B[n,k] (+bias_m[m]) (+bias_n[n])
// A: [M,ldA] fp16 row-major, B: [N,ldB] fp16 row-major. M,N mult 128, K mult 64.
// 256 threads, 8 warps 2(m)x4(n), warp tile 64x32, CTA 128x128, 3-stage, 96KB.
// out_kind: 0 = f32, 1 = f16
__global__ void __launch_bounds__(256)
gemm_f16_mma(const __half* __restrict__ A, const __half* __restrict__ B,
             void* __restrict__ Cv, int out_kind,
             const float* __restrict__ bias_m, const float* __restrict__ bias_n,
             int M, int N, int K, int ldA, int ldB,
             long long sA, long long sB, long long sC)
{
    extern __shared__ char smem[];
    const uint32_t sb = smem_u32(smem);
    const int tid = threadIdx.x, wid = tid >> 5, lane = tid & 31;
    const int wm = wid & 1, wn = wid >> 1;
    const int m_w = wm * 64, n_w = wn * 32;

    uint32_t bufA[STAGES], bufB[STAGES];
#pragma unroll
    for (int s = 0; s < STAGES; s++) { bufA[s] = sb + s * 32768; bufB[s] = bufA[s] + 16384; }

    const int m0 = blockIdx.y * 128, n0 = blockIdx.x * 128;
    const char* Ab = (const char*)(A + (long long)blockIdx.z * sA + (long long)m0 * ldA);
    const char* Bb = (const char*)(B + (long long)blockIdx.z * sB + (long long)n0 * ldB);
    const long long rbA = (long long)ldA * 2;
    const long long rbB = (long long)ldB * 2;
    const int nc = K >> 6;

    const int lrow = tid >> 3;
    const int lcol = (tid & 7) << 4;

    auto load_chunk = [&](int c, int s) {
        const char* ga = Ab + (long long)c * 128;
        const char* gb = Bb + (long long)c * 128;
#pragma unroll
        for (int i = 0; i < 4; i++) {
            int row = lrow + i * 32;
            uint32_t off = SWZ128((uint32_t)(row * 128 + lcol));
            long long go = (long long)row;
            cp16(bufA[s] + off, ga + go * rbA + lcol);
            cp16(bufB[s] + off, gb + go * rbB + lcol);
        }
    };

    uint32_t acc[4][4][2];
#pragma unroll
    for (int i = 0; i < 4; i++)
#pragma unroll
        for (int j = 0; j < 4; j++) { acc[i][j][0] = 0u; acc[i][j][1] = 0u; }

    const int grp = lane >> 3, rw = lane & 7;
    const int a_row = (grp & 1) * 8 + rw;
    const int a_kh  = (grp >> 1) * 16;
    const int b_row = (grp >> 1) * 8 + rw;
    const int b_kh  = (grp & 1) * 16;

    load_chunk(0, 0); CP_COMMIT();
    if (nc > 1) { load_chunk(1, 1); CP_COMMIT(); }

    for (int c = 0; c < nc; c++) {
        if (c + 1 < nc) { CP_WAIT(1); } else { CP_WAIT(0); }
        __syncthreads();
        if (c + 2 < nc) { load_chunk(c + 2, (c + 2) % STAGES); CP_COMMIT(); }
        const uint32_t sa = bufA[c % STAGES], sbm = bufB[c % STAGES];
#pragma unroll
        for (int kk = 0; kk < 4; kk++) {
            const int kb = kk * 32;
            uint32_t a[4][4], b[4][2];
#pragma unroll
            for (int mt = 0; mt < 4; mt++) {
                int row = m_w + mt * 16 + a_row;
                uint32_t ad = sa + SWZ128((uint32_t)(row * 128 + kb + a_kh));
                ldmx4(a[mt][0], a[mt][1], a[mt][2], a[mt][3], ad);
            }
#pragma unroll
            for (int np = 0; np < 2; np++) {
                int row = n_w + np * 16 + b_row;
                uint32_t bd = sbm + SWZ128((uint32_t)(row * 128 + kb + b_kh));
                uint32_t r0, r1, r2, r3;
                ldmx4(r0, r1, r2, r3, bd);
                b[np * 2][0] = r0; b[np * 2][1] = r1;
                b[np * 2 + 1][0] = r2; b[np * 2 + 1][1] = r3;
            }
#pragma unroll
            for (int mt = 0; mt < 4; mt++)
#pragma unroll
                for (int nt = 0; nt < 4; nt++)
                    mma_f16(acc[mt][nt], a[mt], b[nt]);
        }
    }

    // epilogue: reg q of acc[mt][nt] holds row (r_lo + q*8), cols c_off, c_off+1 (packed half2)
    const int r_lo = lane >> 2, c_off = (lane & 3) * 2;
#pragma unroll
    for (int mt = 0; mt < 4; mt++) {
        int row = m0 + m_w + mt * 16 + r_lo;
#pragma unroll
        for (int half = 0; half < 2; half++) {
            int r = row + half * 8;
            float bmv = bias_m ? bias_m[r] : 0.f;
            long long base = (long long)blockIdx.z * sC + (long long)r * N + n0 + n_w + c_off;
#pragma unroll
            for (int nt = 0; nt < 4; nt++) {
                float2 v = __half22float2(*reinterpret_cast<__half2*>(&acc[mt][nt][half]));
                v.x += bmv; v.y += bmv;
                int col = n0 + n_w + nt * 8 + c_off;
                if (bias_n) { v.x += bias_n[col]; v.y += bias_n[col + 1]; }
                if (out_kind == 1) {
                    *reinterpret_cast<__half2*>((__half*)Cv + base + nt * 8) =
                        __floats2half2_rn(v.x, v.y);
                } else {
                    *reinterpret_cast<float2*>((float*)Cv + base + nt * 8) = v;
                }
            }
        }
    }
}

// ================= bf16 HMMA TN GEMM (fp32 accumulate; wz branch) =================
__global__ void __launch_bounds__(256)
gemm_bf16_mma(const __nv_bfloat16* __restrict__ A, const __nv_bfloat16* __restrict__ B,
              float* __restrict__ Cv,
              const float* __restrict__ bias_m,
              int M, int N, int K, int ldA, int ldB,
              long long sA, long long sB, long long sC)
{
    extern __shared__ char smem[];
    const uint32_t sb = smem_u32(smem);
    const int tid = threadIdx.x, wid = tid >> 5, lane = tid & 31;
    const int wm = wid & 1, wn = wid >> 1;
    const int m_w = wm * 64, n_w = wn * 32;

    uint32_t bufA[STAGES], bufB[STAGES];
#pragma unroll
    for (int s = 0; s < STAGES; s++) { bufA[s] = sb + s * 32768; bufB[s] = bufA[s] + 16384; }

    const int m0 = blockIdx.y * 128, n0 = blockIdx.x * 128;
    const char* Ab = (const char*)(A + (long long)blockIdx.z * sA + (long long)m0 * ldA);
    const char* Bb = (const char*)(B + (long long)blockIdx.z * sB + (long long)n0 * ldB);
    const long long rbA = (long long)ldA * 2;
    const long long rbB = (long long)ldB * 2;
    const int nc = K >> 6;

    const int lrow = tid >> 3;
    const int lcol = (tid & 7) << 4;

    auto load_chunk = [&](int c, int s) {
        const char* ga = Ab + (long long)c * 128;
        const char* gb = Bb + (long long)c * 128;
#pragma unroll
        for (int i = 0; i < 4; i++) {
            int row = lrow + i * 32;
            uint32_t off = SWZ128((uint32_t)(row * 128 + lcol));
            long long go = (long long)row;
            cp16(bufA[s] + off, ga + go * rbA + lcol);
            cp16(bufB[s] + off, gb + go * rbB + lcol);
        }
    };

    float acc[4][4][4];
#pragma unroll
    for (int i = 0; i < 4; i++)
#pragma unroll
        for (int j = 0; j < 4; j++)
#pragma unroll
            for (int q = 0; q < 4; q++) acc[i][j][q] = 0.f;

    const int grp = lane >> 3, rw = lane & 7;
    const int a_row = (grp & 1) * 8 + rw;
    const int a_kh  = (grp >> 1) * 16;
    const int b_row = (grp >> 1) * 8 + rw;
    const int b_kh  = (grp & 1) * 16;

    load_chunk(0, 0); CP_COMMIT();
    if (nc > 1) { load_chunk(1, 1); CP_COMMIT(); }

    for (int c = 0; c < nc; c++) {
        if (c + 1 < nc) { CP_WAIT(1); } else { CP_WAIT(0); }
        __syncthreads();
        if (c + 2 < nc) { load_chunk(c + 2, (c + 2) % STAGES); CP_COMMIT(); }
        const uint32_t sa = bufA[c % STAGES], sbm = bufB[c % STAGES];
#pragma unroll
        for (int kk = 0; kk < 4; kk++) {
            const int kb = kk * 32;
            uint32_t a[4][4], b[4][2];
#pragma unroll
            for (int mt = 0; mt < 4; mt++) {
                int row = m_w + mt * 16 + a_row;
                uint32_t ad = sa + SWZ128((uint32_t)(row * 128 + kb + a_kh));
                ldmx4(a[mt][0], a[mt][1], a[mt][2], a[mt][3], ad);
            }
#pragma unroll
            for (int np = 0; np < 2; np++) {
                int row = n_w + np * 16 + b_row;
                uint32_t bd = sbm + SWZ128((uint32_t)(row * 128 + kb + b_kh));
                uint32_t r0, r1, r2, r3;
                ldmx4(r0, r1, r2, r3, bd);
                b[np * 2][0] = r0; b[np * 2][1] = r1;
                b[np * 2 + 1][0] = r2; b[np * 2 + 1][1] = r3;
            }
#pragma unroll
            for (int mt = 0; mt < 4; mt++)
#pragma unroll
                for (int nt = 0; nt < 4; nt++)
                    mma_bf16(acc[mt][nt], a[mt], b[nt]);
        }
    }

    const int r_lo = lane >> 2, c_off = (lane & 3) * 2;
#pragma unroll
    for (int mt = 0; mt < 4; mt++) {
        int row = m0 + m_w + mt * 16 + r_lo;
#pragma unroll
        for (int half = 0; half < 2; half++) {
            int r = row + half * 8;
            float bmv = bias_m ? bias_m[r] : 0.f;
            long long base = (long long)blockIdx.z * sC + (long long)r * N + n0 + n_w + c_off;
#pragma unroll
            for (int nt = 0; nt < 4; nt++) {
                float v0 = acc[mt][nt][half * 2 + 0] + bmv;
                float v1 = acc[mt][nt][half * 2 + 1] + bmv;
                *reinterpret_cast<float2*>(Cv + base + nt * 8) = make_float2(v0, v1);
            }
        }
    }
}

// ---------------- prep: Wh,Wg,Wm -> fp16 [o,c]; bhg = bh|bg ----------------
__global__ void prep_weights(const float* __restrict__ Wh, const float* __restrict__ Wg,
                             const float* __restrict__ Wm, const float* __restrict__ bh,
                             const float* __restrict__ bg, __half* __restrict__ whgm,
                             float* __restrict__ bhg)
{
    int i = blockIdx.x * blockDim.x + threadIdx.x;
    int n = CC * CC;
    if (i < n)               whgm[i] = __float2half(Wh[i]);
    else if (i < 2 * n)      whgm[i] = __float2half(Wg[i - n]);
    else if (i < 3 * n)      whgm[i] = __float2half(Wm[i - 2 * n]);
    else if (i < 3 * n + CC)       bhg[i - 3 * n] = bh[i - 3 * n];
    else if (i < 3 * n + 2 * CC)   bhg[i - 3 * n] = bg[i - 3 * n - CC];
}

// ---------------- Wz [o,c] fp32 -> Wz3 [o, hi|hi|lo] bf16 ----------------
__global__ void split_w(const float* __restrict__ in, __nv_bfloat16* __restrict__ out)
{
    int i = blockIdx.x * blockDim.x + threadIdx.x;
    if (i >= CC * CC) return;
    int o = i / CC, c = i - o * CC;
    float v = in[i];
    __nv_bfloat16 hi = __float2bfloat16(v);
    __nv_bfloat16 lo = __float2bfloat16(v - __bfloat162float(hi));
    out[(long long)o * K3 + c]          = hi;
    out[(long long)o * K3 + CC + c]     = hi;
    out[(long long)o * K3 + 2 * CC + c] = lo;
}

// ---------------- x [c,t] fp32 -> x3 bf16 [t, hi|lo|hi] AND xh fp16 [t,c] ----------------
__global__ void split_x(const float* __restrict__ in, __nv_bfloat16* __restrict__ x3,
                        __half* __restrict__ xh, long long sIn, long long sX3, long long sXh)
{
    __shared__ float tile[32][33];
    const float* ib = in + (long long)blockIdx.z * sIn;
    __nv_bfloat16* o3 = x3 + (long long)blockIdx.z * sX3;
    __half* oh = xh + (long long)blockIdx.z * sXh;
    int t0 = blockIdx.x * 32, c0 = blockIdx.y * 32;
    int x = threadIdx.x, y = threadIdx.y;
#pragma unroll
    for (int i = 0; i < 32; i += 8)
        tile[y + i][x] = ib[(long long)(c0 + y + i) * THW + t0 + x];
    __syncthreads();
#pragma unroll
    for (int i = 0; i < 32; i += 8) {
        float v = tile[x][y + i];
        __nv_bfloat16 hi = __float2bfloat16(v);
        __nv_bfloat16 lo = __float2bfloat16(v - __bfloat162float(hi));
        long long row = (long long)(t0 + y + i) * K3;
        o3[row + c0 + x]          = hi;
        o3[row + CC + c0 + x]     = lo;
        o3[row + 2 * CC + c0 + x] = hi;
        oh[(long long)(t0 + y + i) * CC + c0 + x] = __float2half(v);
    }
}

// ---------------- transpose + fp32->fp16 (mask^T) ----------------
__global__ void transpose_cvt(const float* __restrict__ in, __half* __restrict__ out,
                              long long sIn, long long sOut)
{
    __shared__ float tile[32][33];
    const float* ib = in + (long long)blockIdx.z * sIn;
    __half* ob = out + (long long)blockIdx.z * sOut;
    int t0 = blockIdx.x * 32, c0 = blockIdx.y * 32;
    int x = threadIdx.x, y = threadIdx.y;
#pragma unroll
    for (int i = 0; i < 32; i += 8)
        tile[y + i][x] = ib[(long long)(c0 + y + i) * THW + t0 + x];
    __syncthreads();
#pragma unroll
    for (int i = 0; i < 32; i += 8)
        ob[(long long)(t0 + y + i) * CC + c0 + x] = __float2half(tile[x][y + i]);
}

// ---------------- softmax fp16 in-place (attention) ----------------
__global__ void __launch_bounds__(256)
softmax_h(__half* __restrict__ data, int rowlen)
{
    __half* p = data + (long long)blockIdx.x * rowlen;
    const int tid = threadIdx.x;
    __shared__ float red[8];

    float v[25];
    float mx = -3.0e38f;
#pragma unroll
    for (int i = 0; i < 25; i++) {
        int idx = tid + (i << 8);
        v[i] = (idx < rowlen) ? __half2float(p[idx]) : -3.0e38f;
        mx = fmaxf(mx, v[i]);
    }
#pragma unroll
    for (int o = 16; o; o >>= 1) mx = fmaxf(mx, __shfl_xor_sync(0xffffffffu, mx, o));
    if ((tid & 31) == 0) red[tid >> 5] = mx;
    __syncthreads();
    mx = red[0];
#pragma unroll
    for (int w = 1; w < 8; w++) mx = fmaxf(mx, red[w]);
    __syncthreads();

    float s = 0.f;
#pragma unroll
    for (int i = 0; i < 25; i++) { v[i] = __expf(v[i] - mx); s += v[i]; }
#pragma unroll
    for (int o = 16; o; o >>= 1) s += __shfl_xor_sync(0xffffffffu, s, o);
    if ((tid & 31) == 0) red[tid >> 5] = s;
    __syncthreads();
    s = 0.f;
#pragma unroll
    for (int w = 0; w < 8; w++) s += red[w];
    float inv = 1.f / s;
#pragma unroll
    for (int i = 0; i < 25; i++) {
        int idx = tid + (i << 8);
        if (idx < rowlen) p[idx] = __float2half(v[i] * inv);
    }
}

// ---------------- BN stats on g_wz ----------------
__global__ void __launch_bounds__(256)
bn_stats(const float* __restrict__ wz, const float* __restrict__ bn_w,
         const float* __restrict__ bn_b, float* __restrict__ scale,
         float* __restrict__ shift)
{
    int c = blockIdx.x;
    int tid = threadIdx.x;
    float s = 0.f, sq = 0.f;
    for (int i = tid; i < NB * THW; i += 256) {
        int n = i / THW, t = i - n * THW;
        float v = wz[(long long)n * CT + (long long)c * THW + t];
        s += v;
        sq = fmaf(v, v, sq);
    }
    __shared__ float r1[8], r2[8];
#pragma unroll
    for (int o = 16; o; o >>= 1) {
        s  += __shfl_xor_sync(0xffffffffu, s,  o);
        sq += __shfl_xor_sync(0xffffffffu, sq, o);
    }
    if ((tid & 31) == 0) { r1[tid >> 5] = s; r2[tid >> 5] = sq; }
    __syncthreads();
    if (tid == 0) {
        s = 0.f; sq = 0.f;
#pragma unroll
        for (int w = 0; w < 8; w++) { s += r1[w]; sq += r2[w]; }
        const float invn = 1.f / (float)(NB * THW);
        float mu  = s * invn;
        float var = sq * invn - mu * mu;
        float sc  = bn_w[c] * rsqrtf(var + 1e-5f);
        scale[c] = sc;
        shift[c] = bn_b[c] - mu * sc;
    }
}

// ---------------- fused: mask_atten = softmax_t(me); out = gamma*pm*mask_atten + BN(wz) ----------------
__global__ void __launch_bounds__(256)
softmax_final(const float* __restrict__ me, const __half* __restrict__ pm,
              const float* __restrict__ wz, const float* __restrict__ scale,
              const float* __restrict__ shift, const float* __restrict__ gamma,
              float* __restrict__ out)
{
    const int blk = blockIdx.x;
    const int c = blk % CC;
    const long long base = (long long)blk * THW;
    const float* p = me + base;
    const int tid = threadIdx.x;
    __shared__ float red[8];

    float v[25];
    float mx = -3.0e38f;
#pragma unroll
    for (int i = 0; i < 25; i++) {
        int idx = tid + (i << 8);
        v[i] = (idx < THW) ? p[idx] : -3.0e38f;
        mx = fmaxf(mx, v[i]);
    }
#pragma unroll
    for (int o = 16; o; o >>= 1) mx = fmaxf(mx, __shfl_xor_sync(0xffffffffu, mx, o));
    if ((tid & 31) == 0) red[tid >> 5] = mx;
    __syncthreads();
    mx = red[0];
#pragma unroll
    for (int w = 1; w < 8; w++) mx = fmaxf(mx, red[w]);
    __syncthreads();

    float s = 0.f;
#pragma unroll
    for (int i = 0; i < 25; i++) { v[i] = __expf(v[i] - mx); s += v[i]; }
#pragma unroll
    for (int o = 16; o; o >>= 1) s += __shfl_xor_sync(0xffffffffu, s, o);
    if ((tid & 31) == 0) red[tid >> 5] = s;
    __syncthreads();
    s = 0.f;
#pragma unroll
    for (int w = 0; w < 8; w++) s += red[w];

    const float inv = 1.f / s;
    const float g  = gamma[0];
    const float sc = scale[c], sh = shift[c];
#pragma unroll
    for (int i = 0; i < 25; i++) {
        int idx = tid + (i << 8);
        if (idx < THW) {
            float ma  = v[i] * inv;
            float pmv = __half2float(pm[base + idx]);
            out[base + idx] = g * pmv * ma + fmaf(wz[base + idx], sc, sh);
        }
    }
}

// ---------------- launch ----------------
extern "C" void kernel_launch(void* const* d_in, const int* in_sizes, int n_in,
                              void* d_out, int out_size)
{
    const float* x    = (const float*)d_in[0];
    const float* mask = (const float*)d_in[1];
    const float* Wh   = (const float*)d_in[2];
    const float* bh   = (const float*)d_in[3];
    const float* Wg   = (const float*)d_in[4];
    const float* bg   = (const float*)d_in[5];
    const float* Wm   = (const float*)d_in[6];
    const float* bm   = (const float*)d_in[7];
    const float* Wz   = (const float*)d_in[8];
    const float* bz   = (const float*)d_in[9];
    const float* bn_w = (const float*)d_in[10];
    const float* bn_b = (const float*)d_in[11];
    const float* gamma= (const float*)d_in[12];
    float* out = (float*)d_out;

    float *wz, *me, *bhg, *scale, *shift;
    __nv_bfloat16 *x3, *Wz3;
    __half *att, *xh, *maskT, *whgm, *phxpg, *phm, *pm;
    cudaGetSymbolAddress((void**)&wz,    g_wz);
    cudaGetSymbolAddress((void**)&me,    g_me);
    cudaGetSymbolAddress((void**)&att,   g_att);
    cudaGetSymbolAddress((void**)&x3,    g_x3);
    cudaGetSymbolAddress((void**)&Wz3,   g_Wz3);
    cudaGetSymbolAddress((void**)&xh,    g_xh);
    cudaGetSymbolAddress((void**)&maskT, g_maskT);
    cudaGetSymbolAddress((void**)&whgm,  g_whgm);
    cudaGetSymbolAddress((void**)&phxpg, g_phxpg);
    cudaGetSymbolAddress((void**)&phm,   g_phm);
    cudaGetSymbolAddress((void**)&pm,    g_pm);
    cudaGetSymbolAddress((void**)&bhg,   g_bhg);
    cudaGetSymbolAddress((void**)&scale, g_scale);
    cudaGetSymbolAddress((void**)&shift, g_shift);

    const long long EE = (long long)EEL;
    const long long sX3 = (long long)THW * K3;
    const long long sHG = (long long)THW * 1024;
    const int SMEM_GEMM = STAGES * 32768;   // 96KB
    cudaFuncSetAttribute(gemm_f16_mma,  cudaFuncAttributeMaxDynamicSharedMemorySize, SMEM_GEMM);
    cudaFuncSetAttribute(gemm_bf16_mma, cudaFuncAttributeMaxDynamicSharedMemorySize, SMEM_GEMM);

    const dim3 t32(32, 8);

    // prep (4 launches so the 6th overall launch is a GEMM for ncu -s 5 -c 1)
    prep_weights<<<(3 * CC * CC + 2 * CC + 255) / 256, 256>>>(Wh, Wg, Wm, bh, bg, whgm, bhg);
    split_w<<<(CC * CC + 255) / 256, 256>>>(Wz, Wz3);
    split_x<<<dim3(THW / 32, CC / 32, NB), t32>>>(x, x3, xh, CT, sX3, CT);
    transpose_cvt<<<dim3(THW / 32, CC / 32, NB), t32>>>(mask, maskT, CT, CT);

    // proj1 (merged phx+pg): phxpg[t,o] = sum_c xh[t,c]*(Wh|Wg)[o,c] + bhg[o]  (f16, N=1024)
    gemm_f16_mma<<<dim3(1024 / 128, THW / 128, NB), 256, SMEM_GEMM>>>(
        xh, whgm, phxpg, 1, nullptr, bhg, THW, 1024, CC, CC, CC, CT, 0, sHG);

    // phm[o,s] = sum_c Wh[o,c]*maskT[s,c] + bh[o]  (f16)
    gemm_f16_mma<<<dim3(THW / 128, CC / 128, NB), 256, SMEM_GEMM>>>(
        whgm, maskT, phm, 1, bh, nullptr, CC, THW, CC, CC, CC, 0, CT, CT);

    // pm[o,t] = sum_c Wm[o,c]*xh[t,c] + bm[o]  (f16)
    gemm_f16_mma<<<dim3(THW / 128, CC / 128, NB), 256, SMEM_GEMM>>>(
        whgm + 2 * CC * CC, xh, pm, 1, bm, nullptr, CC, THW, CC, CC, CC, 0, CT, CT);

    // wz[o,t] near-fp32 via bf16x3 split, K=1536 (fp32 acc)
    gemm_bf16_mma<<<dim3(THW / 128, CC / 128, NB), 256, SMEM_GEMM>>>(
        Wz3, x3, wz, bz, CC, THW, K3, K3, K3, 0, sX3, CT);

    // energy[t,s] = sum_c phx[t,c]*pg[s,c]  (f16 out into att)
    gemm_f16_mma<<<dim3(THW / 128, THW / 128, NB), 256, SMEM_GEMM>>>(
        phxpg, phxpg + 512, att, 1, nullptr, nullptr, THW, THW, CC, 1024, 1024, sHG, sHG, EE);

    // attention = softmax_s(energy), f16 in place
    softmax_h<<<NB * THW, 256>>>(att, THW);

    // mask_energy[c,t] = sum_s phm[c,s]*att[t,s]  (fp32 out, f16 acc)
    gemm_f16_mma<<<dim3(THW / 128, CC / 128, NB), 256, SMEM_GEMM>>>(
        phm, att, me, 0, nullptr, nullptr, CC, THW, THW, THW, THW, CT, EE, CT);

    // BN stats on wz
    bn_stats<<<CC, 256>>>(wz, bn_w, bn_b, scale, shift);

    // fused softmax_t(me) + final combine
    softmax_final<<<NB * CC, 256>>>(me, pm, wz, scale, shift, gamma, out);
}